// round 1
// baseline (speedup 1.0000x reference)
#include <cuda_runtime.h>
#include <math.h>
#include <stdint.h>

// Problem constants
#define BB 2
#define LL 2048
#define DD 512
#define HH 8
#define DKV 64          // DK == DV == 64
#define TOK (BB*LL)     // 4096 tokens
#define OUT_ELEMS (BB*LL*DD)            // 2,097,152 (first output)
// attn output: [H*B, L, L] follows at d_out + OUT_ELEMS

// -------------------- scratch (no allocations allowed) --------------------
__device__ float g_qh[BB*HH*LL*DKV];   // [b*H+h][l][d]
__device__ float g_kh[BB*HH*LL*DKV];
__device__ float g_vh[BB*HH*LL*DKV];
__device__ float g_ctx[BB*LL*DD];      // [b*L+l][h*64+d]
__device__ float g_tmp[BB*LL*DD];      // pre-LayerNorm out

// ===========================================================================
// Kernel 1: projections  qh = q@Wq^T + bq  (and k, v), scattered to
// [b*H+h][l][d] layout.  M=4096, N=512, K=512.  BM=128 BN=128 BK=16.
// ===========================================================================
__global__ __launch_bounds__(256) void proj_kernel(
    const float* __restrict__ q, const float* __restrict__ k, const float* __restrict__ v,
    const float* __restrict__ Wq, const float* __restrict__ bq,
    const float* __restrict__ Wk, const float* __restrict__ bk,
    const float* __restrict__ Wv, const float* __restrict__ bv)
{
    const float *A, *W, *bias;
    float* out;
    int z = blockIdx.z;
    if (z == 0)      { A = q; W = Wq; bias = bq; out = g_qh; }
    else if (z == 1) { A = k; W = Wk; bias = bk; out = g_kh; }
    else             { A = v; W = Wv; bias = bv; out = g_vh; }

    __shared__ float As[16][128 + 4];
    __shared__ float Bs[16][128 + 4];
    const int m0 = blockIdx.y * 128, n0 = blockIdx.x * 128;
    const int tid = threadIdx.x;
    const int tx = tid & 15, ty = tid >> 4;

    float acc[8][8];
    #pragma unroll
    for (int i = 0; i < 8; i++)
        #pragma unroll
        for (int j = 0; j < 8; j++) acc[i][j] = 0.f;

    for (int k0 = 0; k0 < DD; k0 += 16) {
        #pragma unroll
        for (int it = 0; it < 2; it++) {
            int idx = tid + it * 256;         // 0..511 float4s
            int row = idx >> 2, c4 = (idx & 3) * 4;
            float4 f = *(const float4*)(A + (size_t)(m0 + row) * DD + k0 + c4);
            As[c4 + 0][row] = f.x; As[c4 + 1][row] = f.y;
            As[c4 + 2][row] = f.z; As[c4 + 3][row] = f.w;
        }
        #pragma unroll
        for (int it = 0; it < 2; it++) {
            int idx = tid + it * 256;
            int row = idx >> 2, c4 = (idx & 3) * 4;
            float4 f = *(const float4*)(W + (size_t)(n0 + row) * DD + k0 + c4);
            Bs[c4 + 0][row] = f.x; Bs[c4 + 1][row] = f.y;
            Bs[c4 + 2][row] = f.z; Bs[c4 + 3][row] = f.w;
        }
        __syncthreads();
        #pragma unroll
        for (int p = 0; p < 16; p++) {
            float a[8], b[8];
            *(float4*)(a)     = *(const float4*)&As[p][ty * 8];
            *(float4*)(a + 4) = *(const float4*)&As[p][ty * 8 + 4];
            *(float4*)(b)     = *(const float4*)&Bs[p][tx * 8];
            *(float4*)(b + 4) = *(const float4*)&Bs[p][tx * 8 + 4];
            #pragma unroll
            for (int i = 0; i < 8; i++)
                #pragma unroll
                for (int j = 0; j < 8; j++)
                    acc[i][j] = fmaf(a[i], b[j], acc[i][j]);
        }
        __syncthreads();
    }

    // scatter to [b*H+h][l][d]
    const int nbase = n0 + tx * 8;
    const int h = nbase >> 6, d = nbase & 63;   // 8 cols never cross a head
    #pragma unroll
    for (int i = 0; i < 8; i++) {
        int t = m0 + ty * 8 + i;
        int bb = t >> 11, l = t & 2047;
        float r[8];
        #pragma unroll
        for (int j = 0; j < 8; j++) r[j] = acc[i][j] + bias[nbase + j];
        float* o = out + (((size_t)(bb * HH + h)) * LL + l) * DKV + d;
        *(float4*)(o)     = *(float4*)(r);
        *(float4*)(o + 4) = *(float4*)(r + 4);
    }
}

// ===========================================================================
// Kernel 2: scores S = Q @ K^T (unscaled), mask -> -inf, write raw scores to
// attn region of d_out, layout [h*B+b][lq][lk].  Per head: 2048x2048, K=64.
// ===========================================================================
__global__ __launch_bounds__(256) void score_kernel(
    const unsigned char* __restrict__ mask, float* __restrict__ attn)
{
    const int bz = blockIdx.z;            // b*H + h
    const int b = bz >> 3, h = bz & 7;
    const float* Q = g_qh + (size_t)bz * LL * DKV;
    const float* K = g_kh + (size_t)bz * LL * DKV;

    __shared__ float As[32][128 + 4];
    __shared__ float Bs[32][128 + 4];
    const int m0 = blockIdx.y * 128, n0 = blockIdx.x * 128;
    const int tid = threadIdx.x;
    const int tx = tid & 15, ty = tid >> 4;

    float acc[8][8];
    #pragma unroll
    for (int i = 0; i < 8; i++)
        #pragma unroll
        for (int j = 0; j < 8; j++) acc[i][j] = 0.f;

    for (int k0 = 0; k0 < DKV; k0 += 32) {
        #pragma unroll
        for (int it = 0; it < 4; it++) {
            int idx = tid + it * 256;          // 1024 float4s
            int row = idx >> 3, c4 = (idx & 7) * 4;
            float4 f = *(const float4*)(Q + (size_t)(m0 + row) * DKV + k0 + c4);
            As[c4 + 0][row] = f.x; As[c4 + 1][row] = f.y;
            As[c4 + 2][row] = f.z; As[c4 + 3][row] = f.w;
        }
        #pragma unroll
        for (int it = 0; it < 4; it++) {
            int idx = tid + it * 256;
            int row = idx >> 3, c4 = (idx & 7) * 4;
            float4 f = *(const float4*)(K + (size_t)(n0 + row) * DKV + k0 + c4);
            Bs[c4 + 0][row] = f.x; Bs[c4 + 1][row] = f.y;
            Bs[c4 + 2][row] = f.z; Bs[c4 + 3][row] = f.w;
        }
        __syncthreads();
        #pragma unroll
        for (int p = 0; p < 32; p++) {
            float a[8], bf[8];
            *(float4*)(a)      = *(const float4*)&As[p][ty * 8];
            *(float4*)(a + 4)  = *(const float4*)&As[p][ty * 8 + 4];
            *(float4*)(bf)     = *(const float4*)&Bs[p][tx * 8];
            *(float4*)(bf + 4) = *(const float4*)&Bs[p][tx * 8 + 4];
            #pragma unroll
            for (int i = 0; i < 8; i++)
                #pragma unroll
                for (int j = 0; j < 8; j++)
                    acc[i][j] = fmaf(a[i], bf[j], acc[i][j]);
        }
        __syncthreads();
    }

    const int lkbase = n0 + tx * 8;
    #pragma unroll
    for (int i = 0; i < 8; i++) {
        int lq = m0 + ty * 8 + i;
        const unsigned char* mrow = mask + ((size_t)b * LL + lq) * LL + lkbase;
        float* orow = attn + (((size_t)(h * BB + b)) * LL + lq) * LL + lkbase;
        float r[8];
        #pragma unroll
        for (int j = 0; j < 8; j++)
            r[j] = mrow[j] ? -INFINITY : acc[i][j];
        *(float4*)(orow)     = *(float4*)(r);
        *(float4*)(orow + 4) = *(float4*)(r + 4);
    }
}

// ===========================================================================
// Kernel 3: row softmax in-place on attn.  One block per row of 2048.
// ===========================================================================
__global__ __launch_bounds__(256) void softmax_kernel(float* __restrict__ attn)
{
    float* p = attn + (size_t)blockIdx.x * LL;
    const int tid = threadIdx.x;
    __shared__ float redm[8];
    __shared__ float reds[8];

    float4 v0 = ((const float4*)p)[tid];
    float4 v1 = ((const float4*)p)[tid + 256];
    float x[8] = {v0.x, v0.y, v0.z, v0.w, v1.x, v1.y, v1.z, v1.w};

    float mx = x[0];
    #pragma unroll
    for (int i = 1; i < 8; i++) mx = fmaxf(mx, x[i]);
    #pragma unroll
    for (int o = 16; o; o >>= 1) mx = fmaxf(mx, __shfl_xor_sync(0xffffffffu, mx, o));
    if ((tid & 31) == 0) redm[tid >> 5] = mx;
    __syncthreads();
    if (tid < 32) {
        float m = (tid < 8) ? redm[tid] : -INFINITY;
        #pragma unroll
        for (int o = 4; o; o >>= 1) m = fmaxf(m, __shfl_xor_sync(0xffffffffu, m, o));
        if (tid == 0) redm[0] = m;
    }
    __syncthreads();
    const float m = redm[0];

    float s = 0.f;
    #pragma unroll
    for (int i = 0; i < 8; i++) { x[i] = __expf(x[i] - m); s += x[i]; }
    #pragma unroll
    for (int o = 16; o; o >>= 1) s += __shfl_xor_sync(0xffffffffu, s, o);
    if ((tid & 31) == 0) reds[tid >> 5] = s;
    __syncthreads();
    if (tid < 32) {
        float t = (tid < 8) ? reds[tid] : 0.f;
        #pragma unroll
        for (int o = 4; o; o >>= 1) t += __shfl_xor_sync(0xffffffffu, t, o);
        if (tid == 0) reds[0] = t;
    }
    __syncthreads();
    const float inv = 1.f / reds[0];

    float4 w0 = make_float4(x[0]*inv, x[1]*inv, x[2]*inv, x[3]*inv);
    float4 w1 = make_float4(x[4]*inv, x[5]*inv, x[6]*inv, x[7]*inv);
    ((float4*)p)[tid]       = w0;
    ((float4*)p)[tid + 256] = w1;
}

// ===========================================================================
// Kernel 4: ctx = P @ V, per head: [2048x2048] @ [2048x64] -> scatter to
// g_ctx [b*L+l][h*64+d].  BM=128, BN=64, BK=32, 256 thr, 8x4 per thread.
// ===========================================================================
__global__ __launch_bounds__(256) void ctx_kernel(const float* __restrict__ attn)
{
    const int bz = blockIdx.z;
    const int b = bz >> 3, h = bz & 7;
    const float* P = attn + ((size_t)(h * BB + b)) * LL * LL;
    const float* V = g_vh + (size_t)bz * LL * DKV;

    __shared__ float As[32][128 + 4];
    __shared__ float Bs[32][64];
    const int m0 = blockIdx.x * 128;
    const int tid = threadIdx.x;
    const int tx = tid & 15, ty = tid >> 4;

    float acc[8][4];
    #pragma unroll
    for (int i = 0; i < 8; i++)
        #pragma unroll
        for (int j = 0; j < 4; j++) acc[i][j] = 0.f;

    for (int k0 = 0; k0 < LL; k0 += 32) {
        #pragma unroll
        for (int it = 0; it < 4; it++) {
            int idx = tid + it * 256;          // 1024 float4s of P tile
            int row = idx >> 3, c4 = (idx & 7) * 4;
            float4 f = *(const float4*)(P + (size_t)(m0 + row) * LL + k0 + c4);
            As[c4 + 0][row] = f.x; As[c4 + 1][row] = f.y;
            As[c4 + 2][row] = f.z; As[c4 + 3][row] = f.w;
        }
        #pragma unroll
        for (int it = 0; it < 2; it++) {
            int idx = tid + it * 256;          // 512 float4s of V tile
            int row = idx >> 4, c4 = (idx & 15) * 4;
            *(float4*)&Bs[row][c4] = *(const float4*)(V + (size_t)(k0 + row) * DKV + c4);
        }
        __syncthreads();
        #pragma unroll
        for (int p = 0; p < 32; p++) {
            float a[8], bf[4];
            *(float4*)(a)     = *(const float4*)&As[p][ty * 8];
            *(float4*)(a + 4) = *(const float4*)&As[p][ty * 8 + 4];
            *(float4*)(bf)    = *(const float4*)&Bs[p][tx * 4];
            #pragma unroll
            for (int i = 0; i < 8; i++)
                #pragma unroll
                for (int j = 0; j < 4; j++)
                    acc[i][j] = fmaf(a[i], bf[j], acc[i][j]);
        }
        __syncthreads();
    }

    const int d = tx * 4;
    #pragma unroll
    for (int i = 0; i < 8; i++) {
        int lq = m0 + ty * 8 + i;
        float4 r = make_float4(acc[i][0], acc[i][1], acc[i][2], acc[i][3]);
        *(float4*)(g_ctx + ((size_t)b * LL + lq) * DD + h * DKV + d) = r;
    }
}

// ===========================================================================
// Kernel 5: out = ctx @ Wo^T + bo + residual(q) -> g_tmp.  M=4096,N=512,K=512.
// ===========================================================================
__global__ __launch_bounds__(256) void outproj_kernel(
    const float* __restrict__ q, const float* __restrict__ Wo,
    const float* __restrict__ bo)
{
    __shared__ float As[16][128 + 4];
    __shared__ float Bs[16][128 + 4];
    const int m0 = blockIdx.y * 128, n0 = blockIdx.x * 128;
    const int tid = threadIdx.x;
    const int tx = tid & 15, ty = tid >> 4;

    float acc[8][8];
    #pragma unroll
    for (int i = 0; i < 8; i++)
        #pragma unroll
        for (int j = 0; j < 8; j++) acc[i][j] = 0.f;

    for (int k0 = 0; k0 < DD; k0 += 16) {
        #pragma unroll
        for (int it = 0; it < 2; it++) {
            int idx = tid + it * 256;
            int row = idx >> 2, c4 = (idx & 3) * 4;
            float4 f = *(const float4*)(g_ctx + (size_t)(m0 + row) * DD + k0 + c4);
            As[c4 + 0][row] = f.x; As[c4 + 1][row] = f.y;
            As[c4 + 2][row] = f.z; As[c4 + 3][row] = f.w;
        }
        #pragma unroll
        for (int it = 0; it < 2; it++) {
            int idx = tid + it * 256;
            int row = idx >> 2, c4 = (idx & 3) * 4;
            float4 f = *(const float4*)(Wo + (size_t)(n0 + row) * DD + k0 + c4);
            Bs[c4 + 0][row] = f.x; Bs[c4 + 1][row] = f.y;
            Bs[c4 + 2][row] = f.z; Bs[c4 + 3][row] = f.w;
        }
        __syncthreads();
        #pragma unroll
        for (int p = 0; p < 16; p++) {
            float a[8], b[8];
            *(float4*)(a)     = *(const float4*)&As[p][ty * 8];
            *(float4*)(a + 4) = *(const float4*)&As[p][ty * 8 + 4];
            *(float4*)(b)     = *(const float4*)&Bs[p][tx * 8];
            *(float4*)(b + 4) = *(const float4*)&Bs[p][tx * 8 + 4];
            #pragma unroll
            for (int i = 0; i < 8; i++)
                #pragma unroll
                for (int j = 0; j < 8; j++)
                    acc[i][j] = fmaf(a[i], b[j], acc[i][j]);
        }
        __syncthreads();
    }

    const int nbase = n0 + tx * 8;
    #pragma unroll
    for (int i = 0; i < 8; i++) {
        int t = m0 + ty * 8 + i;
        float r[8];
        #pragma unroll
        for (int j = 0; j < 8; j++)
            r[j] = acc[i][j] + bo[nbase + j] + q[(size_t)t * DD + nbase + j];
        float* o = g_tmp + (size_t)t * DD + nbase;
        *(float4*)(o)     = *(float4*)(r);
        *(float4*)(o + 4) = *(float4*)(r + 4);
    }
}

// ===========================================================================
// Kernel 6: LayerNorm per token -> d_out[0 : B*L*D]
// ===========================================================================
__global__ __launch_bounds__(256) void ln_kernel(
    const float* __restrict__ gamma, const float* __restrict__ beta,
    float* __restrict__ out)
{
    const int t = blockIdx.x;
    const float* x = g_tmp + (size_t)t * DD;
    const int tid = threadIdx.x;
    __shared__ float red1[8], red2[8];

    float a = x[tid], b = x[tid + 256];
    float s = a + b;
    float ss = a * a + b * b;
    #pragma unroll
    for (int o = 16; o; o >>= 1) {
        s  += __shfl_xor_sync(0xffffffffu, s, o);
        ss += __shfl_xor_sync(0xffffffffu, ss, o);
    }
    if ((tid & 31) == 0) { red1[tid >> 5] = s; red2[tid >> 5] = ss; }
    __syncthreads();
    if (tid < 32) {
        float u = (tid < 8) ? red1[tid] : 0.f;
        float w = (tid < 8) ? red2[tid] : 0.f;
        #pragma unroll
        for (int o = 4; o; o >>= 1) {
            u += __shfl_xor_sync(0xffffffffu, u, o);
            w += __shfl_xor_sync(0xffffffffu, w, o);
        }
        if (tid == 0) { red1[0] = u; red2[0] = w; }
    }
    __syncthreads();
    const float mu = red1[0] * (1.f / DD);
    const float var = red2[0] * (1.f / DD) - mu * mu;
    const float rstd = rsqrtf(var + 1e-5f);

    out[(size_t)t * DD + tid]       = (a - mu) * rstd * gamma[tid]       + beta[tid];
    out[(size_t)t * DD + tid + 256] = (b - mu) * rstd * gamma[tid + 256] + beta[tid + 256];
}

// ===========================================================================
extern "C" void kernel_launch(void* const* d_in, const int* in_sizes, int n_in,
                              void* d_out, int out_size)
{
    const float* q    = (const float*)d_in[0];
    const float* k    = (const float*)d_in[1];
    const float* v    = (const float*)d_in[2];
    const unsigned char* mask = (const unsigned char*)d_in[3];
    const float* Wq   = (const float*)d_in[4];
    const float* bq   = (const float*)d_in[5];
    const float* Wk   = (const float*)d_in[6];
    const float* bk   = (const float*)d_in[7];
    const float* Wv   = (const float*)d_in[8];
    const float* bv   = (const float*)d_in[9];
    const float* Wo   = (const float*)d_in[10];
    const float* bo   = (const float*)d_in[11];
    const float* gamma = (const float*)d_in[12];
    const float* beta  = (const float*)d_in[13];

    float* out  = (float*)d_out;
    float* attn = out + OUT_ELEMS;      // [H*B, L, L]

    proj_kernel<<<dim3(4, 32, 3), 256>>>(q, k, v, Wq, bq, Wk, bk, Wv, bv);
    score_kernel<<<dim3(16, 16, BB * HH), 256>>>(mask, attn);
    softmax_kernel<<<BB * HH * LL, 256>>>(attn);
    ctx_kernel<<<dim3(16, 1, BB * HH), 256>>>(attn);
    outproj_kernel<<<dim3(4, 32), 256>>>(q, Wo, bo);
    ln_kernel<<<TOK, 256>>>(gamma, beta, out);
}

// round 4
// speedup vs baseline: 1.5139x; 1.5139x over previous
#include <cuda_runtime.h>
#include <cuda_bf16.h>
#include <math.h>
#include <stdint.h>

#define LLS 2048
#define DDM 512
#define NZ  16                 // B*H
#define TOKENS 4096
#define OUT_ELEMS (TOKENS*DDM)
#define SA 72                  // padded K-stride for 64-wide operand tiles
#define SV 136                 // padded K-stride for 128-wide Vt tiles
#define NEGINF __int_as_float(0xff800000)

// ------------------------- scratch (no allocs) -----------------------------
__device__ __nv_bfloat16 g_q_hi[NZ*LLS*64];
__device__ __nv_bfloat16 g_q_lo[NZ*LLS*64];
__device__ __nv_bfloat16 g_k_hi[NZ*LLS*64];
__device__ __nv_bfloat16 g_k_lo[NZ*LLS*64];
__device__ __nv_bfloat16 g_vt_hi[NZ*64*LLS];   // [bz][d][lk]
__device__ __nv_bfloat16 g_vt_lo[NZ*64*LLS];
__device__ __nv_bfloat16 g_ctx_hi[TOKENS*DDM];
__device__ __nv_bfloat16 g_ctx_lo[TOKENS*DDM];
__device__ float g_rowM[NZ*LLS];
__device__ float g_rowI[NZ*LLS];
__device__ float g_tmp[TOKENS*DDM];

// ------------------------------ helpers ------------------------------------
static __device__ __forceinline__ uint32_t cvs(const void* p) {
    uint32_t a;
    asm("{ .reg .u64 t; cvta.to.shared.u64 t, %1; cvt.u32.u64 %0, t; }" : "=r"(a) : "l"(p));
    return a;
}
static __device__ __forceinline__ void ldsm4(uint32_t* r, uint32_t a) {
    asm volatile("ldmatrix.sync.aligned.m8n8.x4.shared.b16 {%0,%1,%2,%3}, [%4];"
        : "=r"(r[0]), "=r"(r[1]), "=r"(r[2]), "=r"(r[3]) : "r"(a));
}
static __device__ __forceinline__ void mma_bf(float* d, const uint32_t* a, uint32_t b0, uint32_t b1) {
    asm volatile("mma.sync.aligned.m16n8k16.row.col.f32.bf16.bf16.f32 "
        "{%0,%1,%2,%3},{%4,%5,%6,%7},{%8,%9},{%0,%1,%2,%3};"
        : "+f"(d[0]), "+f"(d[1]), "+f"(d[2]), "+f"(d[3])
        : "r"(a[0]), "r"(a[1]), "r"(a[2]), "r"(a[3]), "r"(b0), "r"(b1));
}
static __device__ __forceinline__ void st_s2(uint32_t a, uint32_t x, uint32_t y) {
    asm volatile("st.shared.v2.b32 [%0], {%1,%2};" :: "r"(a), "r"(x), "r"(y));
}
static __device__ __forceinline__ void st_s4(uint32_t a, uint4 v) {
    asm volatile("st.shared.v4.b32 [%0], {%1,%2,%3,%4};" :: "r"(a), "r"(v.x), "r"(v.y), "r"(v.z), "r"(v.w));
}
static __device__ __forceinline__ uint32_t pk2(__nv_bfloat16 a, __nv_bfloat16 b) {
    __nv_bfloat162 t = __halves2bfloat162(a, b);
    return *reinterpret_cast<uint32_t*>(&t);
}
static __device__ __forceinline__ void split2(float x, float y, uint32_t& h, uint32_t& l) {
    __nv_bfloat16 hx = __float2bfloat16(x), hy = __float2bfloat16(y);
    h = pk2(hx, hy);
    l = pk2(__float2bfloat16(x - __bfloat162float(hx)),
            __float2bfloat16(y - __bfloat162float(hy)));
}
static __device__ __forceinline__ uint32_t aoff(int row0, int k0, int stride, int lane) {
    return (uint32_t)((row0 + (lane & 15)) * stride + k0 + ((lane >> 4) << 3)) * 2;
}
static __device__ __forceinline__ uint32_t boff(int n0, int k0, int stride, int lane) {
    return (uint32_t)((n0 + ((lane >> 4) << 3) + (lane & 7)) * stride + k0 + (((lane >> 3) & 1) << 3)) * 2;
}

// fp32 [128][64] (row stride ld) -> split hi/lo into smem [128][SA]
static __device__ __forceinline__ void load_split64(const float* __restrict__ src, int ld,
                                                    uint32_t dh, uint32_t dl, int tid) {
    #pragma unroll
    for (int i = 0; i < 8; i++) {
        int idx = i * 256 + tid, row = idx >> 4, c4 = (idx & 15) * 4;
        float4 f = *(const float4*)(src + (size_t)row * ld + c4);
        uint32_t h0, l0, h1, l1;
        split2(f.x, f.y, h0, l0);
        split2(f.z, f.w, h1, l1);
        uint32_t off = (uint32_t)(row * SA + c4) * 2;
        st_s2(dh + off, h0, h1);
        st_s2(dl + off, l0, l1);
    }
}
// bf16 [128][64] (row stride ld) -> smem [128][SA]
static __device__ __forceinline__ void load_bf64(const __nv_bfloat16* __restrict__ src, int ld,
                                                 uint32_t dst, int tid) {
    #pragma unroll
    for (int i = 0; i < 4; i++) {
        int idx = i * 256 + tid, row = idx >> 3, c = (idx & 7) * 8;
        uint4 u = *(const uint4*)(src + (size_t)row * ld + c);
        st_s4(dst + (uint32_t)(row * SA + c) * 2, u);
    }
}
// bf16 [64][128] (row stride ld) -> smem [64][SV]
static __device__ __forceinline__ void load_bf128(const __nv_bfloat16* __restrict__ src, int ld,
                                                  uint32_t dst, int tid) {
    #pragma unroll
    for (int i = 0; i < 4; i++) {
        int idx = i * 256 + tid, row = idx >> 4, c = (idx & 15) * 8;
        uint4 u = *(const uint4*)(src + (size_t)row * ld + c);
        st_s4(dst + (uint32_t)(row * SV + c) * 2, u);
    }
}

// 3-term split GEMM chunk: c[16][4] += A(16 rows at wrow)*B(128 cols), K=64
static __device__ __forceinline__ void mma_chunk128(float (*c)[4],
        uint32_t sAh, uint32_t sAl, uint32_t sBh, uint32_t sBl, int wrow, int lane) {
    #pragma unroll
    for (int seg = 0; seg < 3; seg++) {
        uint32_t sa = (seg < 2) ? sAh : sAl;
        uint32_t sb = (seg == 1) ? sBl : sBh;
        #pragma unroll
        for (int kk = 0; kk < 4; kk++) {
            int k0 = kk * 16;
            uint32_t a[4];
            ldsm4(a, sa + aoff(wrow, k0, SA, lane));
            #pragma unroll
            for (int g = 0; g < 8; g++) {
                uint32_t b[4];
                ldsm4(b, sb + boff(g * 16, k0, SA, lane));
                mma_bf(c[2 * g],     a, b[0], b[1]);
                mma_bf(c[2 * g + 1], a, b[2], b[3]);
            }
        }
    }
}

// ===========================================================================
// Kernel 1: projections.  z=0: qh=q@Wq^T+bq -> [bz][l][d] split bf16
//                         z=1: kh similarly
//                         z=2: vt = (Wv@v^T): C[dim][token] -> g_vt [bz][d][l]
// ===========================================================================
__global__ __launch_bounds__(256) void proj_kernel(
    const float* __restrict__ q, const float* __restrict__ k, const float* __restrict__ v,
    const float* __restrict__ Wq, const float* __restrict__ bq,
    const float* __restrict__ Wk, const float* __restrict__ bk,
    const float* __restrict__ Wv, const float* __restrict__ bv)
{
    extern __shared__ char sm[];
    const int tid = threadIdx.x, lane = tid & 31, w = tid >> 5;
    const int gid = lane >> 2, tq = lane & 3;
    const int z = blockIdx.z;

    const float *A, *B, *bias;
    int m0, n0;
    if (z == 2) { A = Wv; B = v; bias = bv; m0 = blockIdx.x * 128; n0 = blockIdx.y * 128; }
    else {
        A = (z == 0) ? q : k;
        B = (z == 0) ? Wq : Wk;
        bias = (z == 0) ? bq : bk;
        m0 = blockIdx.y * 128; n0 = blockIdx.x * 128;
    }

    uint32_t s0 = cvs(sm);
    uint32_t sAh = s0, sAl = s0 + 18432, sBh = s0 + 36864, sBl = s0 + 55296;

    float c[16][4];
    #pragma unroll
    for (int i = 0; i < 16; i++)
        #pragma unroll
        for (int j = 0; j < 4; j++) c[i][j] = 0.f;

    for (int c8 = 0; c8 < 8; c8++) {
        __syncthreads();
        load_split64(A + (size_t)m0 * DDM + c8 * 64, DDM, sAh, sAl, tid);
        load_split64(B + (size_t)n0 * DDM + c8 * 64, DDM, sBh, sBl, tid);
        __syncthreads();
        mma_chunk128(c, sAh, sAl, sBh, sBl, w * 16, lane);
    }

    if (z < 2) {
        __nv_bfloat16* Ohi = (z == 0) ? g_q_hi : g_k_hi;
        __nv_bfloat16* Olo = (z == 0) ? g_q_lo : g_k_lo;
        #pragma unroll
        for (int g = 0; g < 16; g++) {
            int n = n0 + g * 8 + 2 * tq;
            float b0 = bias[n], b1 = bias[n + 1];
            int head = n >> 6, d = n & 63;
            #pragma unroll
            for (int rr = 0; rr < 2; rr++) {
                int t = m0 + w * 16 + gid + rr * 8;
                int bb = t >> 11, l = t & 2047;
                float v0 = c[g][rr * 2] + b0, v1 = c[g][rr * 2 + 1] + b1;
                uint32_t h, lo;
                split2(v0, v1, h, lo);
                size_t base = (((size_t)(bb * 8 + head)) * LLS + l) * 64 + d;
                *(uint32_t*)(Ohi + base) = h;
                *(uint32_t*)(Olo + base) = lo;
            }
        }
    } else {
        #pragma unroll
        for (int g = 0; g < 16; g++) {
            int n = n0 + g * 8 + 2 * tq;     // token
            int bb = n >> 11, l = n & 2047;
            #pragma unroll
            for (int rr = 0; rr < 2; rr++) {
                int m = m0 + w * 16 + gid + rr * 8;   // dim
                int head = m >> 6, d = m & 63;
                float bm = bias[m];
                float v0 = c[g][rr * 2] + bm, v1 = c[g][rr * 2 + 1] + bm;
                uint32_t h, lo;
                split2(v0, v1, h, lo);
                size_t base = (((size_t)(bb * 8 + head)) * 64 + d) * LLS + l;
                *(uint32_t*)(g_vt_hi + base) = h;
                *(uint32_t*)(g_vt_lo + base) = lo;
            }
        }
    }
}

// ===========================================================================
// Kernel 2: stats — per 128-row stripe, sweep all K tiles, online (max,expsum)
// grid (16 m-tiles, 16 zz);  zz = h*B + b
// ===========================================================================
__global__ __launch_bounds__(256) void stats_kernel(const unsigned char* __restrict__ mask)
{
    extern __shared__ char sm[];
    const int tid = threadIdx.x, lane = tid & 31, w = tid >> 5;
    const int gid = lane >> 2, tq = lane & 3;
    const int m0 = blockIdx.x * 128, zz = blockIdx.y;
    const int h = zz >> 1, b = zz & 1, bz = b * 8 + h;

    uint32_t s0 = cvs(sm);
    uint32_t sQh = s0, sQl = s0 + 18432, sKh = s0 + 36864, sKl = s0 + 55296;

    load_bf64(g_q_hi + ((size_t)bz * LLS + m0) * 64, 64, sQh, tid);
    load_bf64(g_q_lo + ((size_t)bz * LLS + m0) * 64, 64, sQl, tid);

    const int lq0 = m0 + w * 16 + gid;
    float rM0 = NEGINF, rS0 = 0.f, rM1 = NEGINF, rS1 = 0.f;

    for (int nt = 0; nt < 16; nt++) {
        __syncthreads();
        load_bf64(g_k_hi + ((size_t)bz * LLS + nt * 128) * 64, 64, sKh, tid);
        load_bf64(g_k_lo + ((size_t)bz * LLS + nt * 128) * 64, 64, sKl, tid);
        __syncthreads();

        float c[16][4];
        #pragma unroll
        for (int i = 0; i < 16; i++)
            #pragma unroll
            for (int j = 0; j < 4; j++) c[i][j] = 0.f;
        mma_chunk128(c, sQh, sQl, sKh, sKl, w * 16, lane);

        // mask + tile max
        const unsigned char* mr0 = mask + ((size_t)b * LLS + lq0) * LLS + nt * 128;
        const unsigned char* mr1 = mr0 + (size_t)8 * LLS;
        float tm0 = NEGINF, tm1 = NEGINF;
        #pragma unroll
        for (int g = 0; g < 16; g++) {
            int nn = g * 8 + 2 * tq;
            unsigned short mw0 = *(const unsigned short*)(mr0 + nn);
            unsigned short mw1 = *(const unsigned short*)(mr1 + nn);
            if (mw0 & 0xFF) c[g][0] = NEGINF;
            if (mw0 >> 8)   c[g][1] = NEGINF;
            if (mw1 & 0xFF) c[g][2] = NEGINF;
            if (mw1 >> 8)   c[g][3] = NEGINF;
            tm0 = fmaxf(tm0, fmaxf(c[g][0], c[g][1]));
            tm1 = fmaxf(tm1, fmaxf(c[g][2], c[g][3]));
        }
        #pragma unroll
        for (int o = 1; o <= 2; o <<= 1) {
            tm0 = fmaxf(tm0, __shfl_xor_sync(0xffffffffu, tm0, o));
            tm1 = fmaxf(tm1, __shfl_xor_sync(0xffffffffu, tm1, o));
        }
        float nM0 = fmaxf(rM0, tm0), nM1 = fmaxf(rM1, tm1);
        float s0v = 0.f, s1v = 0.f;
        if (nM0 != NEGINF) {
            #pragma unroll
            for (int g = 0; g < 16; g++) s0v += __expf(c[g][0] - nM0) + __expf(c[g][1] - nM0);
        }
        if (nM1 != NEGINF) {
            #pragma unroll
            for (int g = 0; g < 16; g++) s1v += __expf(c[g][2] - nM1) + __expf(c[g][3] - nM1);
        }
        #pragma unroll
        for (int o = 1; o <= 2; o <<= 1) {
            s0v += __shfl_xor_sync(0xffffffffu, s0v, o);
            s1v += __shfl_xor_sync(0xffffffffu, s1v, o);
        }
        if (nM0 != NEGINF) { rS0 = rS0 * __expf(rM0 - nM0) + s0v; rM0 = nM0; }
        if (nM1 != NEGINF) { rS1 = rS1 * __expf(rM1 - nM1) + s1v; rM1 = nM1; }
    }

    if (tq == 0) {
        g_rowM[(size_t)zz * LLS + lq0] = rM0;
        g_rowI[(size_t)zz * LLS + lq0] = 1.f / rS0;
        g_rowM[(size_t)zz * LLS + lq0 + 8] = rM1;
        g_rowI[(size_t)zz * LLS + lq0 + 8] = 1.f / rS1;
    }
}

// ===========================================================================
// Kernel 3: fused pass-2 — recompute S, P = exp(S-M)*I, write P to d_out,
// feed P (register A-fragments) into ctx MMA, write split ctx.
// grid (16 m-tiles, 16 zz)
// ===========================================================================
__global__ __launch_bounds__(256) void pctx_kernel(
    const unsigned char* __restrict__ mask, float* __restrict__ attn)
{
    extern __shared__ char sm[];
    const int tid = threadIdx.x, lane = tid & 31, w = tid >> 5;
    const int gid = lane >> 2, tq = lane & 3;
    const int m0 = blockIdx.x * 128, zz = blockIdx.y;
    const int h = zz >> 1, b = zz & 1, bz = b * 8 + h;

    uint32_t s0 = cvs(sm);
    uint32_t sQh = s0, sQl = s0 + 18432, sKh = s0 + 36864, sKl = s0 + 55296;
    uint32_t sVh = s0 + 73728, sVl = s0 + 91136;

    load_bf64(g_q_hi + ((size_t)bz * LLS + m0) * 64, 64, sQh, tid);
    load_bf64(g_q_lo + ((size_t)bz * LLS + m0) * 64, 64, sQl, tid);

    const int lq0 = m0 + w * 16 + gid;
    const float M0 = g_rowM[(size_t)zz * LLS + lq0];
    const float I0 = g_rowI[(size_t)zz * LLS + lq0];
    const float M1 = g_rowM[(size_t)zz * LLS + lq0 + 8];
    const float I1 = g_rowI[(size_t)zz * LLS + lq0 + 8];

    float cc[8][4];
    #pragma unroll
    for (int i = 0; i < 8; i++)
        #pragma unroll
        for (int j = 0; j < 4; j++) cc[i][j] = 0.f;

    for (int nt = 0; nt < 16; nt++) {
        __syncthreads();
        load_bf64(g_k_hi + ((size_t)bz * LLS + nt * 128) * 64, 64, sKh, tid);
        load_bf64(g_k_lo + ((size_t)bz * LLS + nt * 128) * 64, 64, sKl, tid);
        load_bf128(g_vt_hi + (size_t)bz * 64 * LLS + nt * 128, LLS, sVh, tid);
        load_bf128(g_vt_lo + (size_t)bz * 64 * LLS + nt * 128, LLS, sVl, tid);
        __syncthreads();

        float c[16][4];
        #pragma unroll
        for (int i = 0; i < 16; i++)
            #pragma unroll
            for (int j = 0; j < 4; j++) c[i][j] = 0.f;
        mma_chunk128(c, sQh, sQl, sKh, sKl, w * 16, lane);

        // P = exp(S-M)*I with mask, write to gmem
        const unsigned char* mr0 = mask + ((size_t)b * LLS + lq0) * LLS + nt * 128;
        const unsigned char* mr1 = mr0 + (size_t)8 * LLS;
        float* pr0 = attn + ((size_t)zz * LLS + lq0) * LLS + nt * 128;
        float* pr1 = pr0 + (size_t)8 * LLS;
        #pragma unroll
        for (int g = 0; g < 16; g++) {
            int nn = g * 8 + 2 * tq;
            unsigned short mw0 = *(const unsigned short*)(mr0 + nn);
            unsigned short mw1 = *(const unsigned short*)(mr1 + nn);
            c[g][0] = (mw0 & 0xFF) ? 0.f : __expf(c[g][0] - M0) * I0;
            c[g][1] = (mw0 >> 8)   ? 0.f : __expf(c[g][1] - M0) * I0;
            c[g][2] = (mw1 & 0xFF) ? 0.f : __expf(c[g][2] - M1) * I1;
            c[g][3] = (mw1 >> 8)   ? 0.f : __expf(c[g][3] - M1) * I1;
            *(float2*)(pr0 + nn) = make_float2(c[g][0], c[g][1]);
            *(float2*)(pr1 + nn) = make_float2(c[g][2], c[g][3]);
        }

        // ctx += P @ Vt^T : A-fragments come straight from P registers
        #pragma unroll
        for (int kk = 0; kk < 8; kk++) {
            uint32_t ah[4], al[4];
            split2(c[2 * kk][0],     c[2 * kk][1],     ah[0], al[0]);
            split2(c[2 * kk][2],     c[2 * kk][3],     ah[1], al[1]);
            split2(c[2 * kk + 1][0], c[2 * kk + 1][1], ah[2], al[2]);
            split2(c[2 * kk + 1][2], c[2 * kk + 1][3], ah[3], al[3]);
            #pragma unroll
            for (int g2 = 0; g2 < 4; g2++) {
                uint32_t off = boff(g2 * 16, kk * 16, SV, lane);
                uint32_t bh[4], bl[4];
                ldsm4(bh, sVh + off);
                ldsm4(bl, sVl + off);
                mma_bf(cc[2 * g2],     ah, bh[0], bh[1]);
                mma_bf(cc[2 * g2 + 1], ah, bh[2], bh[3]);
                mma_bf(cc[2 * g2],     ah, bl[0], bl[1]);
                mma_bf(cc[2 * g2 + 1], ah, bl[2], bl[3]);
                mma_bf(cc[2 * g2],     al, bh[0], bh[1]);
                mma_bf(cc[2 * g2 + 1], al, bh[2], bh[3]);
            }
        }
    }

    // write split ctx [token][h*64+d]
    #pragma unroll
    for (int g = 0; g < 8; g++) {
        int d = g * 8 + 2 * tq;
        #pragma unroll
        for (int rr = 0; rr < 2; rr++) {
            int t = b * LLS + lq0 + rr * 8;
            uint32_t hv, lv;
            split2(cc[g][rr * 2], cc[g][rr * 2 + 1], hv, lv);
            size_t base = (size_t)t * DDM + h * 64 + d;
            *(uint32_t*)(g_ctx_hi + base) = hv;
            *(uint32_t*)(g_ctx_lo + base) = lv;
        }
    }
}

// ===========================================================================
// Kernel 4: out = ctx @ Wo^T + bo + residual(q) -> g_tmp
// ===========================================================================
__global__ __launch_bounds__(256) void outproj_kernel(
    const float* __restrict__ q, const float* __restrict__ Wo, const float* __restrict__ bo)
{
    extern __shared__ char sm[];
    const int tid = threadIdx.x, lane = tid & 31, w = tid >> 5;
    const int gid = lane >> 2, tq = lane & 3;
    const int m0 = blockIdx.y * 128, n0 = blockIdx.x * 128;

    uint32_t s0 = cvs(sm);
    uint32_t sAh = s0, sAl = s0 + 18432, sBh = s0 + 36864, sBl = s0 + 55296;

    float c[16][4];
    #pragma unroll
    for (int i = 0; i < 16; i++)
        #pragma unroll
        for (int j = 0; j < 4; j++) c[i][j] = 0.f;

    for (int c8 = 0; c8 < 8; c8++) {
        __syncthreads();
        load_bf64(g_ctx_hi + (size_t)m0 * DDM + c8 * 64, DDM, sAh, tid);
        load_bf64(g_ctx_lo + (size_t)m0 * DDM + c8 * 64, DDM, sAl, tid);
        load_split64(Wo + (size_t)n0 * DDM + c8 * 64, DDM, sBh, sBl, tid);
        __syncthreads();
        mma_chunk128(c, sAh, sAl, sBh, sBl, w * 16, lane);
    }

    #pragma unroll
    for (int g = 0; g < 16; g++) {
        int n = n0 + g * 8 + 2 * tq;
        float b0 = bo[n], b1 = bo[n + 1];
        #pragma unroll
        for (int rr = 0; rr < 2; rr++) {
            int t = m0 + w * 16 + gid + rr * 8;
            const float* res = q + (size_t)t * DDM + n;
            float v0 = c[g][rr * 2] + b0 + res[0];
            float v1 = c[g][rr * 2 + 1] + b1 + res[1];
            *(float2*)(g_tmp + (size_t)t * DDM + n) = make_float2(v0, v1);
        }
    }
}

// ===========================================================================
// Kernel 5: LayerNorm per token -> d_out
// ===========================================================================
__global__ __launch_bounds__(256) void ln_kernel(
    const float* __restrict__ gamma, const float* __restrict__ beta,
    float* __restrict__ out)
{
    const int t = blockIdx.x;
    const float* x = g_tmp + (size_t)t * DDM;
    const int tid = threadIdx.x;
    __shared__ float red1[8], red2[8];

    float a = x[tid], b = x[tid + 256];
    float s = a + b;
    float ss = a * a + b * b;
    #pragma unroll
    for (int o = 16; o; o >>= 1) {
        s  += __shfl_xor_sync(0xffffffffu, s, o);
        ss += __shfl_xor_sync(0xffffffffu, ss, o);
    }
    if ((tid & 31) == 0) { red1[tid >> 5] = s; red2[tid >> 5] = ss; }
    __syncthreads();
    if (tid < 32) {
        float u = (tid < 8) ? red1[tid] : 0.f;
        float wv = (tid < 8) ? red2[tid] : 0.f;
        #pragma unroll
        for (int o = 4; o; o >>= 1) {
            u  += __shfl_xor_sync(0xffffffffu, u, o);
            wv += __shfl_xor_sync(0xffffffffu, wv, o);
        }
        if (tid == 0) { red1[0] = u; red2[0] = wv; }
    }
    __syncthreads();
    const float mu = red1[0] * (1.f / DDM);
    const float var = red2[0] * (1.f / DDM) - mu * mu;
    const float rstd = rsqrtf(var + 1e-5f);

    out[(size_t)t * DDM + tid]       = (a - mu) * rstd * gamma[tid]       + beta[tid];
    out[(size_t)t * DDM + tid + 256] = (b - mu) * rstd * gamma[tid + 256] + beta[tid + 256];
}

// ===========================================================================
extern "C" void kernel_launch(void* const* d_in, const int* in_sizes, int n_in,
                              void* d_out, int out_size)
{
    const float* q     = (const float*)d_in[0];
    const float* k     = (const float*)d_in[1];
    const float* v     = (const float*)d_in[2];
    const unsigned char* mask = (const unsigned char*)d_in[3];
    const float* Wq    = (const float*)d_in[4];
    const float* bq    = (const float*)d_in[5];
    const float* Wk    = (const float*)d_in[6];
    const float* bk    = (const float*)d_in[7];
    const float* Wv    = (const float*)d_in[8];
    const float* bv    = (const float*)d_in[9];
    const float* Wo    = (const float*)d_in[10];
    const float* bo    = (const float*)d_in[11];
    const float* gamma = (const float*)d_in[12];
    const float* beta  = (const float*)d_in[13];

    float* out  = (float*)d_out;
    float* attn = out + OUT_ELEMS;

    static int inited = 0;
    if (!inited) {
        cudaFuncSetAttribute(proj_kernel,    cudaFuncAttributeMaxDynamicSharedMemorySize, 73728);
        cudaFuncSetAttribute(stats_kernel,   cudaFuncAttributeMaxDynamicSharedMemorySize, 73728);
        cudaFuncSetAttribute(pctx_kernel,    cudaFuncAttributeMaxDynamicSharedMemorySize, 108544);
        cudaFuncSetAttribute(outproj_kernel, cudaFuncAttributeMaxDynamicSharedMemorySize, 73728);
        inited = 1;
    }

    proj_kernel<<<dim3(4, 32, 3), 256, 73728>>>(q, k, v, Wq, bq, Wk, bk, Wv, bv);
    stats_kernel<<<dim3(16, 16), 256, 73728>>>(mask);
    pctx_kernel<<<dim3(16, 16), 256, 108544>>>(mask, attn);
    outproj_kernel<<<dim3(4, 32), 256, 73728>>>(q, Wo, bo);
    ln_kernel<<<TOKENS, 256>>>(gamma, beta, out);
}

// round 5
// speedup vs baseline: 1.6610x; 1.0971x over previous
#include <cuda_runtime.h>
#include <cuda_bf16.h>
#include <math.h>
#include <stdint.h>

#define LLS 2048
#define DDM 512
#define NZ  16                 // B*H
#define TOKENS 4096
#define OUT_ELEMS (TOKENS*DDM)
#define SA 72                  // padded K-stride for 64-wide operand tiles
#define SV 136                 // padded K-stride for 128-wide Vt tiles
#define NEGINF __int_as_float(0xff800000)

// ------------------------- scratch (no allocs) -----------------------------
__device__ __align__(16) __nv_bfloat16 g_in_hi[3*TOKENS*DDM];   // q,k,v pre-split
__device__ __align__(16) __nv_bfloat16 g_in_lo[3*TOKENS*DDM];
__device__ __align__(16) __nv_bfloat16 g_w_hi[4*DDM*DDM];       // Wq,Wk,Wv,Wo
__device__ __align__(16) __nv_bfloat16 g_w_lo[4*DDM*DDM];
__device__ __align__(16) __nv_bfloat16 g_q_hi[NZ*LLS*64];
__device__ __align__(16) __nv_bfloat16 g_q_lo[NZ*LLS*64];
__device__ __align__(16) __nv_bfloat16 g_k_hi[NZ*LLS*64];
__device__ __align__(16) __nv_bfloat16 g_k_lo[NZ*LLS*64];
__device__ __align__(16) __nv_bfloat16 g_vt_hi[NZ*64*LLS];      // [bz][d][lk]
__device__ __align__(16) __nv_bfloat16 g_vt_lo[NZ*64*LLS];
__device__ __align__(16) __nv_bfloat16 g_ctx_hi[TOKENS*DDM];
__device__ __align__(16) __nv_bfloat16 g_ctx_lo[TOKENS*DDM];
__device__ float g_rowM[NZ*LLS];
__device__ float g_rowI[NZ*LLS];
__device__ float g_tmp[TOKENS*DDM];

// ------------------------------ helpers ------------------------------------
static __device__ __forceinline__ uint32_t cvs(const void* p) {
    uint32_t a;
    asm("{ .reg .u64 t; cvta.to.shared.u64 t, %1; cvt.u32.u64 %0, t; }" : "=r"(a) : "l"(p));
    return a;
}
static __device__ __forceinline__ void ldsm4(uint32_t* r, uint32_t a) {
    asm volatile("ldmatrix.sync.aligned.m8n8.x4.shared.b16 {%0,%1,%2,%3}, [%4];"
        : "=r"(r[0]), "=r"(r[1]), "=r"(r[2]), "=r"(r[3]) : "r"(a));
}
static __device__ __forceinline__ void mma_bf(float* d, const uint32_t* a, uint32_t b0, uint32_t b1) {
    asm volatile("mma.sync.aligned.m16n8k16.row.col.f32.bf16.bf16.f32 "
        "{%0,%1,%2,%3},{%4,%5,%6,%7},{%8,%9},{%0,%1,%2,%3};"
        : "+f"(d[0]), "+f"(d[1]), "+f"(d[2]), "+f"(d[3])
        : "r"(a[0]), "r"(a[1]), "r"(a[2]), "r"(a[3]), "r"(b0), "r"(b1));
}
#define CPC()  asm volatile("cp.async.commit_group;" ::: "memory")
#define CPW0() asm volatile("cp.async.wait_group 0;" ::: "memory")

static __device__ __forceinline__ void cpa16(uint32_t dst, const void* src) {
    asm volatile("cp.async.cg.shared.global [%0], [%1], 16;" :: "r"(dst), "l"(src));
}
// bf16 [128][64] tile (row stride ld) -> smem [128][SA] via cp.async
static __device__ __forceinline__ void cpa_bf64(const __nv_bfloat16* __restrict__ src, int ld,
                                                uint32_t dst, int tid) {
    #pragma unroll
    for (int i = 0; i < 4; i++) {
        int idx = i * 256 + tid, row = idx >> 3, c = (idx & 7) * 8;
        cpa16(dst + (uint32_t)(row * SA + c) * 2, src + (size_t)row * ld + c);
    }
}
// bf16 [64][128] tile (row stride ld) -> smem [64][SV] via cp.async
static __device__ __forceinline__ void cpa_bf128(const __nv_bfloat16* __restrict__ src, int ld,
                                                 uint32_t dst, int tid) {
    #pragma unroll
    for (int i = 0; i < 4; i++) {
        int idx = i * 256 + tid, row = idx >> 4, c = (idx & 15) * 8;
        cpa16(dst + (uint32_t)(row * SV + c) * 2, src + (size_t)row * ld + c);
    }
}
static __device__ __forceinline__ uint32_t pk2(__nv_bfloat16 a, __nv_bfloat16 b) {
    __nv_bfloat162 t = __halves2bfloat162(a, b);
    return *reinterpret_cast<uint32_t*>(&t);
}
static __device__ __forceinline__ void split2(float x, float y, uint32_t& h, uint32_t& l) {
    __nv_bfloat16 hx = __float2bfloat16(x), hy = __float2bfloat16(y);
    h = pk2(hx, hy);
    l = pk2(__float2bfloat16(x - __bfloat162float(hx)),
            __float2bfloat16(y - __bfloat162float(hy)));
}
static __device__ __forceinline__ uint32_t aoff(int row0, int k0, int stride, int lane) {
    return (uint32_t)((row0 + (lane & 15)) * stride + k0 + ((lane >> 4) << 3)) * 2;
}
static __device__ __forceinline__ uint32_t boff(int n0, int k0, int stride, int lane) {
    return (uint32_t)((n0 + ((lane >> 4) << 3) + (lane & 7)) * stride + k0 + (((lane >> 3) & 1) << 3)) * 2;
}

// 3-term split GEMM chunk: c[16][4] += A(16 rows at wrow)*B(128 cols), K=64
static __device__ __forceinline__ void mma_chunk128(float (*c)[4],
        uint32_t sAh, uint32_t sAl, uint32_t sBh, uint32_t sBl, int wrow, int lane) {
    #pragma unroll
    for (int seg = 0; seg < 3; seg++) {
        uint32_t sa = (seg < 2) ? sAh : sAl;
        uint32_t sb = (seg == 1) ? sBl : sBh;
        #pragma unroll
        for (int kk = 0; kk < 4; kk++) {
            int k0 = kk * 16;
            uint32_t a[4];
            ldsm4(a, sa + aoff(wrow, k0, SA, lane));
            #pragma unroll
            for (int g = 0; g < 8; g++) {
                uint32_t b[4];
                ldsm4(b, sb + boff(g * 16, k0, SA, lane));
                mma_bf(c[2 * g],     a, b[0], b[1]);
                mma_bf(c[2 * g + 1], a, b[2], b[3]);
            }
        }
    }
}

// ===========================================================================
// Kernel 0: pre-split fp32 inputs to bf16 hi/lo.  z: 0..2 = q,k,v; 3..6 = W's
// ===========================================================================
__global__ __launch_bounds__(256) void split_kernel(
    const float* __restrict__ q, const float* __restrict__ k, const float* __restrict__ v,
    const float* __restrict__ Wq, const float* __restrict__ Wk,
    const float* __restrict__ Wv, const float* __restrict__ Wo)
{
    const int z = blockIdx.y;
    const float* src;
    __nv_bfloat16 *hi, *lo;
    int n4;
    if (z < 3) {
        src = (z == 0) ? q : (z == 1) ? k : v;
        hi = g_in_hi + (size_t)z * TOKENS * DDM;
        lo = g_in_lo + (size_t)z * TOKENS * DDM;
        n4 = TOKENS * DDM / 4;
    } else {
        src = (z == 3) ? Wq : (z == 4) ? Wk : (z == 5) ? Wv : Wo;
        hi = g_w_hi + (size_t)(z - 3) * DDM * DDM;
        lo = g_w_lo + (size_t)(z - 3) * DDM * DDM;
        n4 = DDM * DDM / 4;
    }
    for (int i = blockIdx.x * 256 + threadIdx.x; i < n4; i += gridDim.x * 256) {
        float4 f = ((const float4*)src)[i];
        uint32_t h0, l0, h1, l1;
        split2(f.x, f.y, h0, l0);
        split2(f.z, f.w, h1, l1);
        ((uint2*)hi)[i] = make_uint2(h0, h1);
        ((uint2*)lo)[i] = make_uint2(l0, l1);
    }
}

// ===========================================================================
// Kernel 1: projections (pure-bf16, cp.async double-buffered).
//   z=0: qh = q@Wq^T+bq -> [bz][l][d] split;  z=1: kh;  z=2: vt = Wv@v^T
// ===========================================================================
__global__ __launch_bounds__(256) void proj_kernel(
    const float* __restrict__ bq, const float* __restrict__ bk, const float* __restrict__ bv)
{
    extern __shared__ char sm[];
    const int tid = threadIdx.x, lane = tid & 31, w = tid >> 5;
    const int gid = lane >> 2, tq = lane & 3;
    const int z = blockIdx.z;

    const __nv_bfloat16 *Ah, *Al, *Bh, *Bl;
    const float* bias;
    int m0, n0;
    if (z == 2) {
        m0 = blockIdx.x * 128;   // dim
        n0 = blockIdx.y * 128;   // token
        Ah = g_w_hi + (size_t)2 * DDM * DDM + (size_t)m0 * DDM;
        Al = g_w_lo + (size_t)2 * DDM * DDM + (size_t)m0 * DDM;
        Bh = g_in_hi + (size_t)2 * TOKENS * DDM + (size_t)n0 * DDM;
        Bl = g_in_lo + (size_t)2 * TOKENS * DDM + (size_t)n0 * DDM;
        bias = bv;
    } else {
        m0 = blockIdx.y * 128;   // token
        n0 = blockIdx.x * 128;   // out-dim
        Ah = g_in_hi + (size_t)z * TOKENS * DDM + (size_t)m0 * DDM;
        Al = g_in_lo + (size_t)z * TOKENS * DDM + (size_t)m0 * DDM;
        Bh = g_w_hi + (size_t)z * DDM * DDM + (size_t)n0 * DDM;
        Bl = g_w_lo + (size_t)z * DDM * DDM + (size_t)n0 * DDM;
        bias = (z == 0) ? bq : bk;
    }

    uint32_t s0 = cvs(sm);     // stage stride 73728: Ah 0, Al 18432, Bh 36864, Bl 55296

    cpa_bf64(Ah, DDM, s0, tid);
    cpa_bf64(Al, DDM, s0 + 18432, tid);
    cpa_bf64(Bh, DDM, s0 + 36864, tid);
    cpa_bf64(Bl, DDM, s0 + 55296, tid);
    CPC();

    float c[16][4];
    #pragma unroll
    for (int i = 0; i < 16; i++)
        #pragma unroll
        for (int j = 0; j < 4; j++) c[i][j] = 0.f;

    for (int c8 = 0; c8 < 8; c8++) {
        CPW0();
        __syncthreads();
        uint32_t sb = s0 + (c8 & 1) * 73728;
        if (c8 < 7) {
            uint32_t sn = s0 + ((c8 + 1) & 1) * 73728;
            int off = (c8 + 1) * 64;
            cpa_bf64(Ah + off, DDM, sn, tid);
            cpa_bf64(Al + off, DDM, sn + 18432, tid);
            cpa_bf64(Bh + off, DDM, sn + 36864, tid);
            cpa_bf64(Bl + off, DDM, sn + 55296, tid);
            CPC();
        }
        mma_chunk128(c, sb, sb + 18432, sb + 36864, sb + 55296, w * 16, lane);
    }

    if (z < 2) {
        __nv_bfloat16* Ohi = (z == 0) ? g_q_hi : g_k_hi;
        __nv_bfloat16* Olo = (z == 0) ? g_q_lo : g_k_lo;
        #pragma unroll
        for (int g = 0; g < 16; g++) {
            int n = n0 + g * 8 + 2 * tq;
            float b0 = bias[n], b1 = bias[n + 1];
            int head = n >> 6, d = n & 63;
            #pragma unroll
            for (int rr = 0; rr < 2; rr++) {
                int t = m0 + w * 16 + gid + rr * 8;
                int bb = t >> 11, l = t & 2047;
                float v0 = c[g][rr * 2] + b0, v1 = c[g][rr * 2 + 1] + b1;
                uint32_t h, lo;
                split2(v0, v1, h, lo);
                size_t base = (((size_t)(bb * 8 + head)) * LLS + l) * 64 + d;
                *(uint32_t*)(Ohi + base) = h;
                *(uint32_t*)(Olo + base) = lo;
            }
        }
    } else {
        #pragma unroll
        for (int g = 0; g < 16; g++) {
            int n = n0 + g * 8 + 2 * tq;     // token
            int bb = n >> 11, l = n & 2047;
            #pragma unroll
            for (int rr = 0; rr < 2; rr++) {
                int m = m0 + w * 16 + gid + rr * 8;   // dim
                int head = m >> 6, d = m & 63;
                float bm = bias[m];
                float v0 = c[g][rr * 2] + bm, v1 = c[g][rr * 2 + 1] + bm;
                uint32_t h, lo;
                split2(v0, v1, h, lo);
                size_t base = (((size_t)(bb * 8 + head)) * 64 + d) * LLS + l;
                *(uint32_t*)(g_vt_hi + base) = h;
                *(uint32_t*)(g_vt_lo + base) = lo;
            }
        }
    }
}

// ===========================================================================
// Kernel 2: stats — Q resident, K tiles cp.async double-buffered.
// ===========================================================================
__global__ __launch_bounds__(256) void stats_kernel(const unsigned char* __restrict__ mask)
{
    extern __shared__ char sm[];
    const int tid = threadIdx.x, lane = tid & 31, w = tid >> 5;
    const int gid = lane >> 2, tq = lane & 3;
    const int m0 = blockIdx.x * 128, zz = blockIdx.y;
    const int h = zz >> 1, b = zz & 1, bz = b * 8 + h;

    uint32_t s0 = cvs(sm);
    uint32_t sQh = s0, sQl = s0 + 18432;
    uint32_t sK = s0 + 36864;   // 2 bufs, stride 36864: hi +0, lo +18432

    const __nv_bfloat16* Kh = g_k_hi + (size_t)bz * LLS * 64;
    const __nv_bfloat16* Kl = g_k_lo + (size_t)bz * LLS * 64;

    cpa_bf64(g_q_hi + ((size_t)bz * LLS + m0) * 64, 64, sQh, tid);
    cpa_bf64(g_q_lo + ((size_t)bz * LLS + m0) * 64, 64, sQl, tid);
    cpa_bf64(Kh, 64, sK, tid);
    cpa_bf64(Kl, 64, sK + 18432, tid);
    CPC();

    const int lq0 = m0 + w * 16 + gid;
    float rM0 = NEGINF, rS0 = 0.f, rM1 = NEGINF, rS1 = 0.f;

    for (int nt = 0; nt < 16; nt++) {
        CPW0();
        __syncthreads();
        uint32_t sb = sK + (nt & 1) * 36864;
        if (nt < 15) {
            uint32_t sn = sK + ((nt + 1) & 1) * 36864;
            cpa_bf64(Kh + (size_t)(nt + 1) * 128 * 64, 64, sn, tid);
            cpa_bf64(Kl + (size_t)(nt + 1) * 128 * 64, 64, sn + 18432, tid);
            CPC();
        }

        float c[16][4];
        #pragma unroll
        for (int i = 0; i < 16; i++)
            #pragma unroll
            for (int j = 0; j < 4; j++) c[i][j] = 0.f;
        mma_chunk128(c, sQh, sQl, sb, sb + 18432, w * 16, lane);

        const unsigned char* mr0 = mask + ((size_t)b * LLS + lq0) * LLS + nt * 128;
        const unsigned char* mr1 = mr0 + (size_t)8 * LLS;
        float tm0 = NEGINF, tm1 = NEGINF;
        #pragma unroll
        for (int g = 0; g < 16; g++) {
            int nn = g * 8 + 2 * tq;
            unsigned short mw0 = *(const unsigned short*)(mr0 + nn);
            unsigned short mw1 = *(const unsigned short*)(mr1 + nn);
            if (mw0 & 0xFF) c[g][0] = NEGINF;
            if (mw0 >> 8)   c[g][1] = NEGINF;
            if (mw1 & 0xFF) c[g][2] = NEGINF;
            if (mw1 >> 8)   c[g][3] = NEGINF;
            tm0 = fmaxf(tm0, fmaxf(c[g][0], c[g][1]));
            tm1 = fmaxf(tm1, fmaxf(c[g][2], c[g][3]));
        }
        #pragma unroll
        for (int o = 1; o <= 2; o <<= 1) {
            tm0 = fmaxf(tm0, __shfl_xor_sync(0xffffffffu, tm0, o));
            tm1 = fmaxf(tm1, __shfl_xor_sync(0xffffffffu, tm1, o));
        }
        float nM0 = fmaxf(rM0, tm0), nM1 = fmaxf(rM1, tm1);
        float s0v = 0.f, s1v = 0.f;
        if (nM0 != NEGINF) {
            #pragma unroll
            for (int g = 0; g < 16; g++) s0v += __expf(c[g][0] - nM0) + __expf(c[g][1] - nM0);
        }
        if (nM1 != NEGINF) {
            #pragma unroll
            for (int g = 0; g < 16; g++) s1v += __expf(c[g][2] - nM1) + __expf(c[g][3] - nM1);
        }
        #pragma unroll
        for (int o = 1; o <= 2; o <<= 1) {
            s0v += __shfl_xor_sync(0xffffffffu, s0v, o);
            s1v += __shfl_xor_sync(0xffffffffu, s1v, o);
        }
        if (nM0 != NEGINF) { rS0 = rS0 * __expf(rM0 - nM0) + s0v; rM0 = nM0; }
        if (nM1 != NEGINF) { rS1 = rS1 * __expf(rM1 - nM1) + s1v; rM1 = nM1; }
    }

    if (tq == 0) {
        g_rowM[(size_t)zz * LLS + lq0] = rM0;
        g_rowI[(size_t)zz * LLS + lq0] = 1.f / rS0;
        g_rowM[(size_t)zz * LLS + lq0 + 8] = rM1;
        g_rowI[(size_t)zz * LLS + lq0 + 8] = 1.f / rS1;
    }
}

// ===========================================================================
// Kernel 3: fused pass-2 — recompute S, P = exp(S-M)*I, write P, feed P
// register fragments into ctx MMA, write split ctx.  K,V double-buffered.
// ===========================================================================
__global__ __launch_bounds__(256) void pctx_kernel(
    const unsigned char* __restrict__ mask, float* __restrict__ attn)
{
    extern __shared__ char sm[];
    const int tid = threadIdx.x, lane = tid & 31, w = tid >> 5;
    const int gid = lane >> 2, tq = lane & 3;
    const int m0 = blockIdx.x * 128, zz = blockIdx.y;
    const int h = zz >> 1, b = zz & 1, bz = b * 8 + h;

    uint32_t s0 = cvs(sm);
    uint32_t sQh = s0, sQl = s0 + 18432;
    uint32_t sK = s0 + 36864;                 // 2 bufs stride 36864 (hi/lo)
    uint32_t sV = s0 + 110592;                // 2 bufs stride 34816 (hi/lo 17408)

    const __nv_bfloat16* Kh = g_k_hi + (size_t)bz * LLS * 64;
    const __nv_bfloat16* Kl = g_k_lo + (size_t)bz * LLS * 64;
    const __nv_bfloat16* Vh = g_vt_hi + (size_t)bz * 64 * LLS;
    const __nv_bfloat16* Vl = g_vt_lo + (size_t)bz * 64 * LLS;

    cpa_bf64(g_q_hi + ((size_t)bz * LLS + m0) * 64, 64, sQh, tid);
    cpa_bf64(g_q_lo + ((size_t)bz * LLS + m0) * 64, 64, sQl, tid);
    cpa_bf64(Kh, 64, sK, tid);
    cpa_bf64(Kl, 64, sK + 18432, tid);
    cpa_bf128(Vh, LLS, sV, tid);
    cpa_bf128(Vl, LLS, sV + 17408, tid);
    CPC();

    const int lq0 = m0 + w * 16 + gid;
    const float M0 = g_rowM[(size_t)zz * LLS + lq0];
    const float I0 = g_rowI[(size_t)zz * LLS + lq0];
    const float M1 = g_rowM[(size_t)zz * LLS + lq0 + 8];
    const float I1 = g_rowI[(size_t)zz * LLS + lq0 + 8];

    float cc[8][4];
    #pragma unroll
    for (int i = 0; i < 8; i++)
        #pragma unroll
        for (int j = 0; j < 4; j++) cc[i][j] = 0.f;

    for (int nt = 0; nt < 16; nt++) {
        CPW0();
        __syncthreads();
        uint32_t sKb = sK + (nt & 1) * 36864;
        uint32_t sVb = sV + (nt & 1) * 34816;
        if (nt < 15) {
            uint32_t sKn = sK + ((nt + 1) & 1) * 36864;
            uint32_t sVn = sV + ((nt + 1) & 1) * 34816;
            cpa_bf64(Kh + (size_t)(nt + 1) * 128 * 64, 64, sKn, tid);
            cpa_bf64(Kl + (size_t)(nt + 1) * 128 * 64, 64, sKn + 18432, tid);
            cpa_bf128(Vh + (nt + 1) * 128, LLS, sVn, tid);
            cpa_bf128(Vl + (nt + 1) * 128, LLS, sVn + 17408, tid);
            CPC();
        }

        float c[16][4];
        #pragma unroll
        for (int i = 0; i < 16; i++)
            #pragma unroll
            for (int j = 0; j < 4; j++) c[i][j] = 0.f;
        mma_chunk128(c, sQh, sQl, sKb, sKb + 18432, w * 16, lane);

        const unsigned char* mr0 = mask + ((size_t)b * LLS + lq0) * LLS + nt * 128;
        const unsigned char* mr1 = mr0 + (size_t)8 * LLS;
        float* pr0 = attn + ((size_t)zz * LLS + lq0) * LLS + nt * 128;
        float* pr1 = pr0 + (size_t)8 * LLS;
        #pragma unroll
        for (int g = 0; g < 16; g++) {
            int nn = g * 8 + 2 * tq;
            unsigned short mw0 = *(const unsigned short*)(mr0 + nn);
            unsigned short mw1 = *(const unsigned short*)(mr1 + nn);
            c[g][0] = (mw0 & 0xFF) ? 0.f : __expf(c[g][0] - M0) * I0;
            c[g][1] = (mw0 >> 8)   ? 0.f : __expf(c[g][1] - M0) * I0;
            c[g][2] = (mw1 & 0xFF) ? 0.f : __expf(c[g][2] - M1) * I1;
            c[g][3] = (mw1 >> 8)   ? 0.f : __expf(c[g][3] - M1) * I1;
            *(float2*)(pr0 + nn) = make_float2(c[g][0], c[g][1]);
            *(float2*)(pr1 + nn) = make_float2(c[g][2], c[g][3]);
        }

        // ctx += P @ Vt^T : A-fragments come straight from P registers
        #pragma unroll
        for (int kk = 0; kk < 8; kk++) {
            uint32_t ah[4], al[4];
            split2(c[2 * kk][0],     c[2 * kk][1],     ah[0], al[0]);
            split2(c[2 * kk][2],     c[2 * kk][3],     ah[1], al[1]);
            split2(c[2 * kk + 1][0], c[2 * kk + 1][1], ah[2], al[2]);
            split2(c[2 * kk + 1][2], c[2 * kk + 1][3], ah[3], al[3]);
            #pragma unroll
            for (int g2 = 0; g2 < 4; g2++) {
                uint32_t off = boff(g2 * 16, kk * 16, SV, lane);
                uint32_t bh[4], bl[4];
                ldsm4(bh, sVb + off);
                ldsm4(bl, sVb + 17408 + off);
                mma_bf(cc[2 * g2],     ah, bh[0], bh[1]);
                mma_bf(cc[2 * g2 + 1], ah, bh[2], bh[3]);
                mma_bf(cc[2 * g2],     ah, bl[0], bl[1]);
                mma_bf(cc[2 * g2 + 1], ah, bl[2], bl[3]);
                mma_bf(cc[2 * g2],     al, bh[0], bh[1]);
                mma_bf(cc[2 * g2 + 1], al, bh[2], bh[3]);
            }
        }
    }

    // write split ctx [token][h*64+d]
    #pragma unroll
    for (int g = 0; g < 8; g++) {
        int d = g * 8 + 2 * tq;
        #pragma unroll
        for (int rr = 0; rr < 2; rr++) {
            int t = b * LLS + lq0 + rr * 8;
            uint32_t hv, lv;
            split2(cc[g][rr * 2], cc[g][rr * 2 + 1], hv, lv);
            size_t base = (size_t)t * DDM + h * 64 + d;
            *(uint32_t*)(g_ctx_hi + base) = hv;
            *(uint32_t*)(g_ctx_lo + base) = lv;
        }
    }
}

// ===========================================================================
// Kernel 4: out = ctx @ Wo^T + bo + residual(q) -> g_tmp  (double-buffered)
// ===========================================================================
__global__ __launch_bounds__(256) void outproj_kernel(
    const float* __restrict__ q, const float* __restrict__ bo)
{
    extern __shared__ char sm[];
    const int tid = threadIdx.x, lane = tid & 31, w = tid >> 5;
    const int gid = lane >> 2, tq = lane & 3;
    const int m0 = blockIdx.y * 128, n0 = blockIdx.x * 128;

    const __nv_bfloat16* Ah = g_ctx_hi + (size_t)m0 * DDM;
    const __nv_bfloat16* Al = g_ctx_lo + (size_t)m0 * DDM;
    const __nv_bfloat16* Bh = g_w_hi + (size_t)3 * DDM * DDM + (size_t)n0 * DDM;
    const __nv_bfloat16* Bl = g_w_lo + (size_t)3 * DDM * DDM + (size_t)n0 * DDM;

    uint32_t s0 = cvs(sm);

    cpa_bf64(Ah, DDM, s0, tid);
    cpa_bf64(Al, DDM, s0 + 18432, tid);
    cpa_bf64(Bh, DDM, s0 + 36864, tid);
    cpa_bf64(Bl, DDM, s0 + 55296, tid);
    CPC();

    float c[16][4];
    #pragma unroll
    for (int i = 0; i < 16; i++)
        #pragma unroll
        for (int j = 0; j < 4; j++) c[i][j] = 0.f;

    for (int c8 = 0; c8 < 8; c8++) {
        CPW0();
        __syncthreads();
        uint32_t sb = s0 + (c8 & 1) * 73728;
        if (c8 < 7) {
            uint32_t sn = s0 + ((c8 + 1) & 1) * 73728;
            int off = (c8 + 1) * 64;
            cpa_bf64(Ah + off, DDM, sn, tid);
            cpa_bf64(Al + off, DDM, sn + 18432, tid);
            cpa_bf64(Bh + off, DDM, sn + 36864, tid);
            cpa_bf64(Bl + off, DDM, sn + 55296, tid);
            CPC();
        }
        mma_chunk128(c, sb, sb + 18432, sb + 36864, sb + 55296, w * 16, lane);
    }

    #pragma unroll
    for (int g = 0; g < 16; g++) {
        int n = n0 + g * 8 + 2 * tq;
        float b0 = bo[n], b1 = bo[n + 1];
        #pragma unroll
        for (int rr = 0; rr < 2; rr++) {
            int t = m0 + w * 16 + gid + rr * 8;
            const float* res = q + (size_t)t * DDM + n;
            float v0 = c[g][rr * 2] + b0 + res[0];
            float v1 = c[g][rr * 2 + 1] + b1 + res[1];
            *(float2*)(g_tmp + (size_t)t * DDM + n) = make_float2(v0, v1);
        }
    }
}

// ===========================================================================
// Kernel 5: LayerNorm per token -> d_out
// ===========================================================================
__global__ __launch_bounds__(256) void ln_kernel(
    const float* __restrict__ gamma, const float* __restrict__ beta,
    float* __restrict__ out)
{
    const int t = blockIdx.x;
    const float* x = g_tmp + (size_t)t * DDM;
    const int tid = threadIdx.x;
    __shared__ float red1[8], red2[8];

    float a = x[tid], b = x[tid + 256];
    float s = a + b;
    float ss = a * a + b * b;
    #pragma unroll
    for (int o = 16; o; o >>= 1) {
        s  += __shfl_xor_sync(0xffffffffu, s, o);
        ss += __shfl_xor_sync(0xffffffffu, ss, o);
    }
    if ((tid & 31) == 0) { red1[tid >> 5] = s; red2[tid >> 5] = ss; }
    __syncthreads();
    if (tid < 32) {
        float u = (tid < 8) ? red1[tid] : 0.f;
        float wv = (tid < 8) ? red2[tid] : 0.f;
        #pragma unroll
        for (int o = 4; o; o >>= 1) {
            u  += __shfl_xor_sync(0xffffffffu, u, o);
            wv += __shfl_xor_sync(0xffffffffu, wv, o);
        }
        if (tid == 0) { red1[0] = u; red2[0] = wv; }
    }
    __syncthreads();
    const float mu = red1[0] * (1.f / DDM);
    const float var = red2[0] * (1.f / DDM) - mu * mu;
    const float rstd = rsqrtf(var + 1e-5f);

    out[(size_t)t * DDM + tid]       = (a - mu) * rstd * gamma[tid]       + beta[tid];
    out[(size_t)t * DDM + tid + 256] = (b - mu) * rstd * gamma[tid + 256] + beta[tid + 256];
}

// ===========================================================================
extern "C" void kernel_launch(void* const* d_in, const int* in_sizes, int n_in,
                              void* d_out, int out_size)
{
    const float* q     = (const float*)d_in[0];
    const float* k     = (const float*)d_in[1];
    const float* v     = (const float*)d_in[2];
    const unsigned char* mask = (const unsigned char*)d_in[3];
    const float* Wq    = (const float*)d_in[4];
    const float* bq    = (const float*)d_in[5];
    const float* Wk    = (const float*)d_in[6];
    const float* bk    = (const float*)d_in[7];
    const float* Wv    = (const float*)d_in[8];
    const float* bv    = (const float*)d_in[9];
    const float* Wo    = (const float*)d_in[10];
    const float* bo    = (const float*)d_in[11];
    const float* gamma = (const float*)d_in[12];
    const float* beta  = (const float*)d_in[13];

    float* out  = (float*)d_out;
    float* attn = out + OUT_ELEMS;

    static int inited = 0;
    if (!inited) {
        cudaFuncSetAttribute(proj_kernel,    cudaFuncAttributeMaxDynamicSharedMemorySize, 147456);
        cudaFuncSetAttribute(stats_kernel,   cudaFuncAttributeMaxDynamicSharedMemorySize, 110592);
        cudaFuncSetAttribute(pctx_kernel,    cudaFuncAttributeMaxDynamicSharedMemorySize, 180224);
        cudaFuncSetAttribute(outproj_kernel, cudaFuncAttributeMaxDynamicSharedMemorySize, 147456);
        inited = 1;
    }

    split_kernel<<<dim3(256, 7), 256>>>(q, k, v, Wq, Wk, Wv, Wo);
    proj_kernel<<<dim3(4, 32, 3), 256, 147456>>>(bq, bk, bv);
    stats_kernel<<<dim3(16, 16), 256, 110592>>>(mask);
    pctx_kernel<<<dim3(16, 16), 256, 180224>>>(mask, attn);
    outproj_kernel<<<dim3(4, 32), 256, 147456>>>(q, bo);
    ln_kernel<<<TOKENS, 256>>>(gamma, beta, out);
}